// round 15
// baseline (speedup 1.0000x reference)
#include <cuda_runtime.h>
#include <cuda_fp16.h>
#include <cstdint>

#define M_TOT 32768
#define H_DIM 1024
#define L_DIM 4096

// ---------------- device scratch (no allocs allowed) ----------------
__device__ __half g_xh [(size_t)M_TOT * H_DIM];
__device__ __half g_Wl [(size_t)L_DIM * H_DIM];
__device__ __half g_Ws [(size_t)H_DIM * H_DIM];
__device__ __half g_c1 [(size_t)L_DIM * L_DIM];
__device__ __half g_c2 [(size_t)H_DIM * L_DIM];
__device__ __half g_b1 [(size_t)M_TOT * L_DIM];
__device__ __half g_b2 [(size_t)M_TOT * L_DIM];
__device__ float  g_acc[(size_t)M_TOT * H_DIM];

// ---------------- helpers ----------------
__device__ __forceinline__ uint32_t s2u(const void* p) {
    uint32_t a;
    asm("{ .reg .u64 t; cvta.to.shared.u64 t, %1; cvt.u32.u64 %0, t; }" : "=r"(a) : "l"(p));
    return a;
}

__device__ __forceinline__ void cpa16(uint32_t dst, const void* src) {
    asm volatile("cp.async.cg.shared.global [%0], [%1], 16;" :: "r"(dst), "l"(src));
}

#define LDM4(r, a)                                                               \
    asm volatile("ldmatrix.sync.aligned.m8n8.x4.shared.b16 {%0,%1,%2,%3}, [%4];" \
                 : "=r"((r)[0]), "=r"((r)[1]), "=r"((r)[2]), "=r"((r)[3])        \
                 : "r"(a))

#define MMA(dd, a, b)                                                             \
    asm volatile("mma.sync.aligned.m16n8k16.row.col.f32.f16.f16.f32 "             \
                 "{%0,%1,%2,%3},{%4,%5,%6,%7},{%8,%9},{%0,%1,%2,%3};"             \
                 : "+f"((dd)[0]), "+f"((dd)[1]), "+f"((dd)[2]), "+f"((dd)[3])     \
                 : "r"((a)[0]), "r"((a)[1]), "r"((a)[2]), "r"((a)[3]),            \
                   "r"((b)[0]), "r"((b)[1]))

// ---------------- fused prep kernel (all rounds in one launch) ---------------
__device__ __forceinline__ uint2 round4h(float4 v) {
    __half2 h01 = __floats2half2_rn(v.x, v.y);
    __half2 h23 = __floats2half2_rn(v.z, v.w);
    uint2 hh;
    hh.x = *(uint32_t*)&h01; hh.y = *(uint32_t*)&h23;
    return hh;
}

// Region block counts (exact: elems/4/256)
#define NB_X  32768   // x:  32768x1024
#define NB_WL 4096    // W_large: 4096x1024
#define NB_C1 16384   // W_c1: 4096x4096
#define NB_C2 4096    // W_c2: 1024x4096
#define NB_WS 1024    // Wsum: 1024x1024

__global__ void __launch_bounds__(256)
k_prep(const float* __restrict__ x,
       const float* __restrict__ W_large, const float* __restrict__ s_large,
       const float* __restrict__ W_c1, const float* __restrict__ W_c2,
       const float* __restrict__ W_s1, const float* __restrict__ s_s1,
       const float* __restrict__ W_s2, const float* __restrict__ s_s2,
       __half* __restrict__ xh, __half* __restrict__ Wl, __half* __restrict__ c1,
       __half* __restrict__ c2, __half* __restrict__ Ws) {
    const int b = blockIdx.x;
    const int tid = threadIdx.x;
    if (b < NB_X) {
        size_t i = (size_t)b * 256 + tid;
        ((uint2*)xh)[i] = round4h(((const float4*)x)[i]);
    } else if (b < NB_X + NB_WL) {
        size_t i = (size_t)(b - NB_X) * 256 + tid;
        size_t idx = i * 4;
        int o = (int)(idx / H_DIM), h = (int)(idx % H_DIM);
        float sc = s_large[(o >> 7) * (H_DIM >> 7) + (h >> 7)];
        float4 v = ((const float4*)W_large)[i];
        v.x *= sc; v.y *= sc; v.z *= sc; v.w *= sc;
        ((uint2*)Wl)[i] = round4h(v);
    } else if (b < NB_X + NB_WL + NB_C1) {
        size_t i = (size_t)(b - NB_X - NB_WL) * 256 + tid;
        ((uint2*)c1)[i] = round4h(((const float4*)W_c1)[i]);
    } else if (b < NB_X + NB_WL + NB_C1 + NB_C2) {
        size_t i = (size_t)(b - NB_X - NB_WL - NB_C1) * 256 + tid;
        ((uint2*)c2)[i] = round4h(((const float4*)W_c2)[i]);
    } else {
        size_t i = (size_t)(b - NB_X - NB_WL - NB_C1 - NB_C2) * 256 + tid;
        size_t idx = i * 4;
        int o = (int)(idx / H_DIM), h = (int)(idx % H_DIM);
        int sb = (o >> 7) * (H_DIM >> 7) + (h >> 7);
        float a = s_s1[sb], bb = s_s2[sb];
        float4 v1 = ((const float4*)W_s1)[i];
        float4 v2 = ((const float4*)W_s2)[i];
        float4 v = make_float4(v1.x * a + v2.x * bb, v1.y * a + v2.y * bb,
                               v1.z * a + v2.z * bb, v1.w * a + v2.w * bb);
        ((uint2*)Ws)[i] = round4h(v);
    }
}

// ---------------- mma.sync single-term fp16 GEMM -----------------------------
// C[M,N] = A[M,K] @ B[N,K]^T.  CTA tile 64(M) x 128(N), BK=64, 2-stage pipe,
// 256 threads (8 warps as 2(M) x 4(N), warp tile 32x32), 4 CTAs/SM.
// SMEM stage: A (64 x 144B) | B (128 x 144B)  (128B data + 16B pad).
#define ROW_B 144
#define A_BUF (64 * ROW_B)            // 9216
#define B_BUF (128 * ROW_B)           // 18432
#define STB_SZ (A_BUF + B_BUF)        // 27648
#define SMEM_TOTAL (2 * STB_SZ)       // 55296

__global__ void __launch_bounds__(256, 4)
gemm_relu(const __half* __restrict__ A, const __half* __restrict__ B,
          __half* __restrict__ Oh, int N, int K) {
    extern __shared__ char smem[];
    const uint32_t sbase = s2u(smem);

    const int tid = threadIdx.x;
    const int lane = tid & 31;
    const int w = tid >> 5;
    const int wm = w & 1;      // 2 warps in M (32 rows each)
    const int wn = w >> 1;     // 4 warps in N (32 cols each)

    const size_t mBase = (size_t)blockIdx.y * 64;
    const size_t nBase = (size_t)blockIdx.x * 128;
    const int NC = K >> 6;     // K-chunks of 64

    const __half* pA = A + mBase * K;
    const __half* pB = B + nBase * K;

    float d[2][4][4];
#pragma unroll
    for (int i = 0; i < 2; i++)
#pragma unroll
        for (int j = 0; j < 4; j++)
#pragma unroll
            for (int q = 0; q < 4; q++) d[i][j][q] = 0.0f;

#define LOAD_CHUNK(c, s)                                                 \
    do {                                                                 \
        const uint32_t stb = sbase + (uint32_t)(s) * STB_SZ;             \
        const size_t kt = (size_t)(c) << 6;                              \
        _Pragma("unroll")                                                \
        for (int i = 0; i < 2; i++) {                                    \
            int ch = tid + i * 256;                                      \
            int row = ch >> 3, kc = ch & 7;                              \
            size_t go = (size_t)row * K + kt + (size_t)kc * 8;           \
            uint32_t so = (uint32_t)(row * ROW_B + kc * 16);             \
            cpa16(stb + so, pA + go);                                    \
        }                                                                \
        _Pragma("unroll")                                                \
        for (int i = 0; i < 4; i++) {                                    \
            int ch = tid + i * 256;                                      \
            int row = ch >> 3, kc = ch & 7;                              \
            size_t go = (size_t)row * K + kt + (size_t)kc * 8;           \
            uint32_t so = (uint32_t)(row * ROW_B + kc * 16);             \
            cpa16(stb + A_BUF + so, pB + go);                            \
        }                                                                \
        asm volatile("cp.async.commit_group;" ::: "memory");             \
    } while (0)

    LOAD_CHUNK(0, 0);

    const uint32_t aRowOff = (uint32_t)(lane & 15) * ROW_B + ((lane >> 4) << 4);
    const uint32_t bRowOff = (uint32_t)((lane & 7) + ((lane >> 4) << 3)) * ROW_B +
                             (((lane >> 3) & 1) << 4);

    for (int c = 0; c < NC; c++) {
        const int s = c & 1;
        asm volatile("cp.async.wait_group 0;" ::: "memory");
        __syncthreads();

        if (c + 1 < NC) LOAD_CHUNK(c + 1, s ^ 1);

        const uint32_t stb = sbase + (uint32_t)s * STB_SZ;
        const uint32_t aP = stb + (uint32_t)(wm * 32) * ROW_B + aRowOff;
        const uint32_t bP = stb + A_BUF + (uint32_t)(wn * 32) * ROW_B + bRowOff;

#pragma unroll
        for (int ks = 0; ks < 4; ks++) {
            const uint32_t kb = (uint32_t)ks * 32;
            uint32_t af[2][4], bb[4][2];
#pragma unroll
            for (int mi = 0; mi < 2; mi++)
                LDM4(af[mi], aP + (uint32_t)(mi * 16) * ROW_B + kb);
#pragma unroll
            for (int g = 0; g < 2; g++)
                LDM4(&bb[g * 2][0], bP + (uint32_t)(g * 16) * ROW_B + kb);

#pragma unroll
            for (int mi = 0; mi < 2; mi++)
#pragma unroll
                for (int ni = 0; ni < 4; ni++) MMA(d[mi][ni], af[mi], bb[ni]);
        }
    }
#undef LOAD_CHUNK

    // ---------------- epilogue: relu + fp16 ----------------
    {
        const int r = lane >> 2;
        const int q = lane & 3;
#pragma unroll
        for (int mi = 0; mi < 2; mi++) {
            const size_t m0 = mBase + (size_t)(wm * 32 + mi * 16 + r);
#pragma unroll
            for (int ni = 0; ni < 4; ni++) {
                const size_t col = nBase + (size_t)(wn * 32 + ni * 8 + q * 2);
                float* dd = d[mi][ni];
                float v0 = fmaxf(dd[0], 0.0f), v1 = fmaxf(dd[1], 0.0f);
                float v2 = fmaxf(dd[2], 0.0f), v3 = fmaxf(dd[3], 0.0f);
                *(__half2*)(Oh + m0 * N + col)       = __floats2half2_rn(v0, v1);
                *(__half2*)(Oh + (m0 + 8) * N + col) = __floats2half2_rn(v2, v3);
            }
        }
    }
}

// ---------- concatenated-K GEMM: Cf = A1 @ B1^T + A2 @ B2^T (fp32 out) ------
// K1 = L_DIM (b2 @ Wc2^T), K2 = H_DIM (x @ Wsum^T), compile-time constants.
__global__ void __launch_bounds__(256, 4)
gemm_cat(const __half* __restrict__ A1, const __half* __restrict__ B1,
         const __half* __restrict__ A2, const __half* __restrict__ B2,
         float* __restrict__ Cf, int N) {
    extern __shared__ char smem[];
    const uint32_t sbase = s2u(smem);

    const int tid = threadIdx.x;
    const int lane = tid & 31;
    const int w = tid >> 5;
    const int wm = w & 1;
    const int wn = w >> 1;

    const size_t mBase = (size_t)blockIdx.y * 64;
    const size_t nBase = (size_t)blockIdx.x * 128;
    const int NC1 = L_DIM >> 6;               // 64
    const int NCT = NC1 + (H_DIM >> 6);       // 80

    const __half* pA1 = A1 + mBase * L_DIM;
    const __half* pB1 = B1 + nBase * L_DIM;
    const __half* pA2 = A2 + mBase * H_DIM;
    const __half* pB2 = B2 + nBase * H_DIM;

    float d[2][4][4];
#pragma unroll
    for (int i = 0; i < 2; i++)
#pragma unroll
        for (int j = 0; j < 4; j++)
#pragma unroll
            for (int q = 0; q < 4; q++) d[i][j][q] = 0.0f;

#define LOAD_CHUNK1(c, s)                                                \
    do {                                                                 \
        const uint32_t stb = sbase + (uint32_t)(s) * STB_SZ;             \
        const size_t kt = (size_t)(c) << 6;                              \
        _Pragma("unroll")                                                \
        for (int i = 0; i < 2; i++) {                                    \
            int ch = tid + i * 256;                                      \
            int row = ch >> 3, kc = ch & 7;                              \
            size_t go = (size_t)row * L_DIM + kt + (size_t)kc * 8;       \
            uint32_t so = (uint32_t)(row * ROW_B + kc * 16);             \
            cpa16(stb + so, pA1 + go);                                   \
        }                                                                \
        _Pragma("unroll")                                                \
        for (int i = 0; i < 4; i++) {                                    \
            int ch = tid + i * 256;                                      \
            int row = ch >> 3, kc = ch & 7;                              \
            size_t go = (size_t)row * L_DIM + kt + (size_t)kc * 8;       \
            uint32_t so = (uint32_t)(row * ROW_B + kc * 16);             \
            cpa16(stb + A_BUF + so, pB1 + go);                           \
        }                                                                \
        asm volatile("cp.async.commit_group;" ::: "memory");             \
    } while (0)

#define LOAD_CHUNK2(c, s)                                                \
    do {                                                                 \
        const uint32_t stb = sbase + (uint32_t)(s) * STB_SZ;             \
        const size_t kt = (size_t)(c) << 6;                              \
        _Pragma("unroll")                                                \
        for (int i = 0; i < 2; i++) {                                    \
            int ch = tid + i * 256;                                      \
            int row = ch >> 3, kc = ch & 7;                              \
            size_t go = (size_t)row * H_DIM + kt + (size_t)kc * 8;       \
            uint32_t so = (uint32_t)(row * ROW_B + kc * 16);             \
            cpa16(stb + so, pA2 + go);                                   \
        }                                                                \
        _Pragma("unroll")                                                \
        for (int i = 0; i < 4; i++) {                                    \
            int ch = tid + i * 256;                                      \
            int row = ch >> 3, kc = ch & 7;                              \
            size_t go = (size_t)row * H_DIM + kt + (size_t)kc * 8;       \
            uint32_t so = (uint32_t)(row * ROW_B + kc * 16);             \
            cpa16(stb + A_BUF + so, pB2 + go);                           \
        }                                                                \
        asm volatile("cp.async.commit_group;" ::: "memory");             \
    } while (0)

#define CAT_LOAD(cc, ss)                                                 \
    do {                                                                 \
        int _c = (cc);                                                   \
        if (_c < NC1) LOAD_CHUNK1(_c, (ss));                             \
        else          LOAD_CHUNK2(_c - NC1, (ss));                       \
    } while (0)

    CAT_LOAD(0, 0);

    const uint32_t aRowOff = (uint32_t)(lane & 15) * ROW_B + ((lane >> 4) << 4);
    const uint32_t bRowOff = (uint32_t)((lane & 7) + ((lane >> 4) << 3)) * ROW_B +
                             (((lane >> 3) & 1) << 4);

    for (int c = 0; c < NCT; c++) {
        const int s = c & 1;
        asm volatile("cp.async.wait_group 0;" ::: "memory");
        __syncthreads();

        if (c + 1 < NCT) CAT_LOAD(c + 1, s ^ 1);

        const uint32_t stb = sbase + (uint32_t)s * STB_SZ;
        const uint32_t aP = stb + (uint32_t)(wm * 32) * ROW_B + aRowOff;
        const uint32_t bP = stb + A_BUF + (uint32_t)(wn * 32) * ROW_B + bRowOff;

#pragma unroll
        for (int ks = 0; ks < 4; ks++) {
            const uint32_t kb = (uint32_t)ks * 32;
            uint32_t af[2][4], bb[4][2];
#pragma unroll
            for (int mi = 0; mi < 2; mi++)
                LDM4(af[mi], aP + (uint32_t)(mi * 16) * ROW_B + kb);
#pragma unroll
            for (int g = 0; g < 2; g++)
                LDM4(&bb[g * 2][0], bP + (uint32_t)(g * 16) * ROW_B + kb);

#pragma unroll
            for (int mi = 0; mi < 2; mi++)
#pragma unroll
                for (int ni = 0; ni < 4; ni++) MMA(d[mi][ni], af[mi], bb[ni]);
        }
    }
#undef CAT_LOAD
#undef LOAD_CHUNK1
#undef LOAD_CHUNK2

    // epilogue: pure fp32 write
    {
        const int r = lane >> 2;
        const int q = lane & 3;
#pragma unroll
        for (int mi = 0; mi < 2; mi++) {
            const size_t m0 = mBase + (size_t)(wm * 32 + mi * 16 + r);
#pragma unroll
            for (int ni = 0; ni < 4; ni++) {
                const size_t col = nBase + (size_t)(wn * 32 + ni * 8 + q * 2);
                float* dd = d[mi][ni];
                *(float2*)(Cf + m0 * N + col)       = make_float2(dd[0], dd[1]);
                *(float2*)(Cf + (m0 + 8) * N + col) = make_float2(dd[2], dd[3]);
            }
        }
    }
}

// ---------------- LayerNorm over H=1024 ----------------
__global__ __launch_bounds__(256)
void ln_kernel(const float* __restrict__ acc, const float* __restrict__ gamma,
               const float* __restrict__ beta, float* __restrict__ out) {
    size_t row = blockIdx.x;
    const float* xr = acc + row * H_DIM;
    int tid = threadIdx.x;

    float4 v = ((const float4*)xr)[tid];
    float s = v.x + v.y + v.z + v.w;
    float q = v.x * v.x + v.y * v.y + v.z * v.z + v.w * v.w;
#pragma unroll
    for (int o = 16; o > 0; o >>= 1) {
        s += __shfl_xor_sync(0xFFFFFFFFu, s, o);
        q += __shfl_xor_sync(0xFFFFFFFFu, q, o);
    }
    __shared__ float ss[8], qq[8];
    int w = tid >> 5, l = tid & 31;
    if (l == 0) { ss[w] = s; qq[w] = q; }
    __syncthreads();
    if (w == 0) {
        s = (l < 8) ? ss[l] : 0.0f;
        q = (l < 8) ? qq[l] : 0.0f;
#pragma unroll
        for (int o = 4; o > 0; o >>= 1) {
            s += __shfl_xor_sync(0xFFFFFFFFu, s, o);
            q += __shfl_xor_sync(0xFFFFFFFFu, q, o);
        }
        if (l == 0) { ss[0] = s; qq[0] = q; }
    }
    __syncthreads();

    const float invH = 1.0f / (float)H_DIM;
    float mean = ss[0] * invH;
    float var = qq[0] * invH - mean * mean;
    float inv = rsqrtf(var + 1e-5f);

    float4 g = ((const float4*)gamma)[tid];
    float4 b = ((const float4*)beta)[tid];
    float4 o4;
    o4.x = (v.x - mean) * inv * g.x + b.x;
    o4.y = (v.y - mean) * inv * g.y + b.y;
    o4.z = (v.z - mean) * inv * g.z + b.z;
    o4.w = (v.w - mean) * inv * g.w + b.w;
    ((float4*)(out + row * H_DIM))[tid] = o4;
}

// ---------------- launch ----------------
extern "C" void kernel_launch(void* const* d_in, const int* in_sizes, int n_in,
                              void* d_out, int out_size) {
    const float* x       = (const float*)d_in[0];
    const float* W_large = (const float*)d_in[1];
    const float* W_s1    = (const float*)d_in[2];
    const float* W_s2    = (const float*)d_in[3];
    const float* W_c1    = (const float*)d_in[4];
    const float* W_c2    = (const float*)d_in[5];
    const float* gamma   = (const float*)d_in[6];
    const float* beta    = (const float*)d_in[7];
    const float* s_large = (const float*)d_in[8];
    const float* s_s1    = (const float*)d_in[9];
    const float* s_s2    = (const float*)d_in[10];
    float* out = (float*)d_out;

    __half *pxh, *pWl, *pWs, *pc1, *pc2, *pb1, *pb2;
    float* pacc;
    cudaGetSymbolAddress((void**)&pxh, g_xh);
    cudaGetSymbolAddress((void**)&pWl, g_Wl);
    cudaGetSymbolAddress((void**)&pWs, g_Ws);
    cudaGetSymbolAddress((void**)&pc1, g_c1);
    cudaGetSymbolAddress((void**)&pc2, g_c2);
    cudaGetSymbolAddress((void**)&pb1, g_b1);
    cudaGetSymbolAddress((void**)&pb2, g_b2);
    cudaGetSymbolAddress((void**)&pacc, g_acc);

    cudaFuncSetAttribute(gemm_relu, cudaFuncAttributeMaxDynamicSharedMemorySize, SMEM_TOTAL);
    cudaFuncSetAttribute(gemm_cat,  cudaFuncAttributeMaxDynamicSharedMemorySize, SMEM_TOTAL);

    // L0: fused prep — all fp16 rounds/folds in one launch
    k_prep<<<NB_X + NB_WL + NB_C1 + NB_C2 + NB_WS, 256>>>(
        x, W_large, s_large, W_c1, W_c2, W_s1, s_s1, W_s2, s_s2,
        pxh, pWl, pc1, pc2, pWs);

    // L1: GEMM1: b1 = fp16(relu(x @ Wl^T))        [M,4096], K=1024
    gemm_relu<<<dim3(L_DIM / 128, M_TOT / 64), 256, SMEM_TOTAL>>>(
        pxh, pWl, pb1, L_DIM, H_DIM);
    // L2: GEMM2: b2 = fp16(relu(b1 @ Wc1^T))      [M,4096], K=4096
    gemm_relu<<<dim3(L_DIM / 128, M_TOT / 64), 256, SMEM_TOTAL>>>(
        pb1, pc1, pb2, L_DIM, L_DIM);
    // L3: fused GEMM3+GEMM4 (concatenated K):     <-- ncu slot
    //     acc = b2 @ Wc2^T (K=4096)  +  x @ Wsum^T (K=1024)
    gemm_cat<<<dim3(H_DIM / 128, M_TOT / 64), 256, SMEM_TOTAL>>>(
        pb2, pc2, pxh, pWs, pacc, H_DIM);
    // L4: LN
    ln_kernel<<<M_TOT, 256>>>(pacc, gamma, beta, out);
}

// round 16
// speedup vs baseline: 1.0149x; 1.0149x over previous
#include <cuda_runtime.h>
#include <cuda_fp16.h>
#include <cstdint>

#define M_TOT 32768
#define H_DIM 1024
#define L_DIM 4096

// ---------------- device scratch (no allocs allowed) ----------------
__device__ __half g_xh [(size_t)M_TOT * H_DIM];
__device__ __half g_Wl [(size_t)L_DIM * H_DIM];
__device__ __half g_Ws [(size_t)H_DIM * H_DIM];
__device__ __half g_c1 [(size_t)L_DIM * L_DIM];
__device__ __half g_c2 [(size_t)H_DIM * L_DIM];
__device__ __half g_b1 [(size_t)M_TOT * L_DIM];
__device__ __half g_b2 [(size_t)M_TOT * L_DIM];
__device__ float  g_acc[(size_t)M_TOT * H_DIM];

// ---------------- helpers ----------------
__device__ __forceinline__ uint32_t s2u(const void* p) {
    uint32_t a;
    asm("{ .reg .u64 t; cvta.to.shared.u64 t, %1; cvt.u32.u64 %0, t; }" : "=r"(a) : "l"(p));
    return a;
}

__device__ __forceinline__ void cpa16(uint32_t dst, const void* src) {
    asm volatile("cp.async.cg.shared.global [%0], [%1], 16;" :: "r"(dst), "l"(src));
}

#define LDM4(r, a)                                                               \
    asm volatile("ldmatrix.sync.aligned.m8n8.x4.shared.b16 {%0,%1,%2,%3}, [%4];" \
                 : "=r"((r)[0]), "=r"((r)[1]), "=r"((r)[2]), "=r"((r)[3])        \
                 : "r"(a))

#define MMA(dd, a, b)                                                             \
    asm volatile("mma.sync.aligned.m16n8k16.row.col.f32.f16.f16.f32 "             \
                 "{%0,%1,%2,%3},{%4,%5,%6,%7},{%8,%9},{%0,%1,%2,%3};"             \
                 : "+f"((dd)[0]), "+f"((dd)[1]), "+f"((dd)[2]), "+f"((dd)[3])     \
                 : "r"((a)[0]), "r"((a)[1]), "r"((a)[2]), "r"((a)[3]),            \
                   "r"((b)[0]), "r"((b)[1]))

// ---------------- fused prep kernel (all rounds in one launch) ---------------
__device__ __forceinline__ uint2 round4h(float4 v) {
    __half2 h01 = __floats2half2_rn(v.x, v.y);
    __half2 h23 = __floats2half2_rn(v.z, v.w);
    uint2 hh;
    hh.x = *(uint32_t*)&h01; hh.y = *(uint32_t*)&h23;
    return hh;
}

// Region block counts (exact: elems/4/256)
#define NB_X  32768   // x:  32768x1024
#define NB_WL 4096    // W_large: 4096x1024
#define NB_C1 16384   // W_c1: 4096x4096
#define NB_C2 4096    // W_c2: 1024x4096
#define NB_WS 1024    // Wsum: 1024x1024

__global__ void __launch_bounds__(256)
k_prep(const float* __restrict__ x,
       const float* __restrict__ W_large, const float* __restrict__ s_large,
       const float* __restrict__ W_c1, const float* __restrict__ W_c2,
       const float* __restrict__ W_s1, const float* __restrict__ s_s1,
       const float* __restrict__ W_s2, const float* __restrict__ s_s2,
       __half* __restrict__ xh, __half* __restrict__ Wl, __half* __restrict__ c1,
       __half* __restrict__ c2, __half* __restrict__ Ws) {
    const int b = blockIdx.x;
    const int tid = threadIdx.x;
    if (b < NB_X) {
        size_t i = (size_t)b * 256 + tid;
        ((uint2*)xh)[i] = round4h(((const float4*)x)[i]);
    } else if (b < NB_X + NB_WL) {
        size_t i = (size_t)(b - NB_X) * 256 + tid;
        size_t idx = i * 4;
        int o = (int)(idx / H_DIM), h = (int)(idx % H_DIM);
        float sc = s_large[(o >> 7) * (H_DIM >> 7) + (h >> 7)];
        float4 v = ((const float4*)W_large)[i];
        v.x *= sc; v.y *= sc; v.z *= sc; v.w *= sc;
        ((uint2*)Wl)[i] = round4h(v);
    } else if (b < NB_X + NB_WL + NB_C1) {
        size_t i = (size_t)(b - NB_X - NB_WL) * 256 + tid;
        ((uint2*)c1)[i] = round4h(((const float4*)W_c1)[i]);
    } else if (b < NB_X + NB_WL + NB_C1 + NB_C2) {
        size_t i = (size_t)(b - NB_X - NB_WL - NB_C1) * 256 + tid;
        ((uint2*)c2)[i] = round4h(((const float4*)W_c2)[i]);
    } else {
        size_t i = (size_t)(b - NB_X - NB_WL - NB_C1 - NB_C2) * 256 + tid;
        size_t idx = i * 4;
        int o = (int)(idx / H_DIM), h = (int)(idx % H_DIM);
        int sb = (o >> 7) * (H_DIM >> 7) + (h >> 7);
        float a = s_s1[sb], bb = s_s2[sb];
        float4 v1 = ((const float4*)W_s1)[i];
        float4 v2 = ((const float4*)W_s2)[i];
        float4 v = make_float4(v1.x * a + v2.x * bb, v1.y * a + v2.y * bb,
                               v1.z * a + v2.z * bb, v1.w * a + v2.w * bb);
        ((uint2*)Ws)[i] = round4h(v);
    }
}

#define ROW_B 144

// ============ gemm_relu: R12/R14 golden config ============
// CTA tile 128x128, BK=64, 3-stage, 512 threads (16 warps 4x4), 2 CTAs/SM.
#define GR_BUF   (128 * ROW_B)        // 18432
#define GR_STB   (2 * GR_BUF)         // 36864
#define GR_NST   3
#define GR_SMEM  (GR_NST * GR_STB)    // 110592

__global__ void __launch_bounds__(512, 2)
gemm_relu(const __half* __restrict__ A, const __half* __restrict__ B,
          __half* __restrict__ Oh, int N, int K) {
    extern __shared__ char smem[];
    const uint32_t sbase = s2u(smem);

    const int tid = threadIdx.x;
    const int lane = tid & 31;
    const int w = tid >> 5;
    const int wm = w & 3;      // 4 warps in M (32 rows each)
    const int wn = w >> 2;     // 4 warps in N (32 cols each)

    const size_t mBase = (size_t)blockIdx.y * 128;
    const size_t nBase = (size_t)blockIdx.x * 128;
    const int NC = K >> 6;     // K-chunks of 64

    const __half* pA = A + mBase * K;
    const __half* pB = B + nBase * K;

    float d[2][4][4];
#pragma unroll
    for (int i = 0; i < 2; i++)
#pragma unroll
        for (int j = 0; j < 4; j++)
#pragma unroll
            for (int q = 0; q < 4; q++) d[i][j][q] = 0.0f;

#define LOAD_CHUNK(c, s)                                                 \
    do {                                                                 \
        const uint32_t stb = sbase + (uint32_t)(s) * GR_STB;             \
        const size_t kt = (size_t)(c) << 6;                              \
        _Pragma("unroll")                                                \
        for (int i = 0; i < 2; i++) {                                    \
            int ch = tid + i * 512;                                      \
            int row = ch >> 3, kc = ch & 7;                              \
            size_t go = (size_t)row * K + kt + (size_t)kc * 8;           \
            uint32_t so = (uint32_t)(row * ROW_B + kc * 16);             \
            cpa16(stb + so,          pA + go);                           \
            cpa16(stb + GR_BUF + so, pB + go);                           \
        }                                                                \
        asm volatile("cp.async.commit_group;" ::: "memory");             \
    } while (0)

    LOAD_CHUNK(0, 0);
    LOAD_CHUNK(1, 1);

    const uint32_t aRowOff = (uint32_t)(lane & 15) * ROW_B + ((lane >> 4) << 4);
    const uint32_t bRowOff = (uint32_t)((lane & 7) + ((lane >> 4) << 3)) * ROW_B +
                             (((lane >> 3) & 1) << 4);

    for (int c = 0; c < NC; c++) {
        const int s = c % GR_NST;
        if (c + 1 < NC) asm volatile("cp.async.wait_group 1;" ::: "memory");
        else            asm volatile("cp.async.wait_group 0;" ::: "memory");
        __syncthreads();

        if (c + 2 < NC) LOAD_CHUNK(c + 2, (c + 2) % GR_NST);

        const uint32_t stb = sbase + (uint32_t)s * GR_STB;
        const uint32_t aP = stb + (uint32_t)(wm * 32) * ROW_B + aRowOff;
        const uint32_t bP = stb + GR_BUF + (uint32_t)(wn * 32) * ROW_B + bRowOff;

#pragma unroll
        for (int ks = 0; ks < 4; ks++) {
            const uint32_t kb = (uint32_t)ks * 32;
            uint32_t af[2][4], bb[4][2];
#pragma unroll
            for (int mi = 0; mi < 2; mi++)
                LDM4(af[mi], aP + (uint32_t)(mi * 16) * ROW_B + kb);
#pragma unroll
            for (int g = 0; g < 2; g++)
                LDM4(&bb[g * 2][0], bP + (uint32_t)(g * 16) * ROW_B + kb);

#pragma unroll
            for (int mi = 0; mi < 2; mi++)
#pragma unroll
                for (int ni = 0; ni < 4; ni++) MMA(d[mi][ni], af[mi], bb[ni]);
        }
    }
#undef LOAD_CHUNK

    // epilogue: relu + fp16
    {
        const int r = lane >> 2;
        const int q = lane & 3;
#pragma unroll
        for (int mi = 0; mi < 2; mi++) {
            const size_t m0 = mBase + (size_t)(wm * 32 + mi * 16 + r);
#pragma unroll
            for (int ni = 0; ni < 4; ni++) {
                const size_t col = nBase + (size_t)(wn * 32 + ni * 8 + q * 2);
                float* dd = d[mi][ni];
                float v0 = fmaxf(dd[0], 0.0f), v1 = fmaxf(dd[1], 0.0f);
                float v2 = fmaxf(dd[2], 0.0f), v3 = fmaxf(dd[3], 0.0f);
                *(__half2*)(Oh + m0 * N + col)       = __floats2half2_rn(v0, v1);
                *(__half2*)(Oh + (m0 + 8) * N + col) = __floats2half2_rn(v2, v3);
            }
        }
    }
}

// ============ gemm_cat: R15 golden config ============
// CTA tile 64(M) x 128(N), BK=64, 2-stage, 256 threads (8 warps 2x4), 4 CTAs/SM.
// Cf = A1 @ B1^T (K=L_DIM) + A2 @ B2^T (K=H_DIM), fp32 out.
#define GC_ABUF  (64 * ROW_B)         // 9216
#define GC_BBUF  (128 * ROW_B)        // 18432
#define GC_STB   (GC_ABUF + GC_BBUF)  // 27648
#define GC_SMEM  (2 * GC_STB)         // 55296

__global__ void __launch_bounds__(256, 4)
gemm_cat(const __half* __restrict__ A1, const __half* __restrict__ B1,
         const __half* __restrict__ A2, const __half* __restrict__ B2,
         float* __restrict__ Cf, int N) {
    extern __shared__ char smem[];
    const uint32_t sbase = s2u(smem);

    const int tid = threadIdx.x;
    const int lane = tid & 31;
    const int w = tid >> 5;
    const int wm = w & 1;
    const int wn = w >> 1;

    const size_t mBase = (size_t)blockIdx.y * 64;
    const size_t nBase = (size_t)blockIdx.x * 128;
    const int NC1 = L_DIM >> 6;               // 64
    const int NCT = NC1 + (H_DIM >> 6);       // 80

    const __half* pA1 = A1 + mBase * L_DIM;
    const __half* pB1 = B1 + nBase * L_DIM;
    const __half* pA2 = A2 + mBase * H_DIM;
    const __half* pB2 = B2 + nBase * H_DIM;

    float d[2][4][4];
#pragma unroll
    for (int i = 0; i < 2; i++)
#pragma unroll
        for (int j = 0; j < 4; j++)
#pragma unroll
            for (int q = 0; q < 4; q++) d[i][j][q] = 0.0f;

#define LOAD_CHUNK1(c, s)                                                \
    do {                                                                 \
        const uint32_t stb = sbase + (uint32_t)(s) * GC_STB;             \
        const size_t kt = (size_t)(c) << 6;                              \
        _Pragma("unroll")                                                \
        for (int i = 0; i < 2; i++) {                                    \
            int ch = tid + i * 256;                                      \
            int row = ch >> 3, kc = ch & 7;                              \
            size_t go = (size_t)row * L_DIM + kt + (size_t)kc * 8;       \
            uint32_t so = (uint32_t)(row * ROW_B + kc * 16);             \
            cpa16(stb + so, pA1 + go);                                   \
        }                                                                \
        _Pragma("unroll")                                                \
        for (int i = 0; i < 4; i++) {                                    \
            int ch = tid + i * 256;                                      \
            int row = ch >> 3, kc = ch & 7;                              \
            size_t go = (size_t)row * L_DIM + kt + (size_t)kc * 8;       \
            uint32_t so = (uint32_t)(row * ROW_B + kc * 16);             \
            cpa16(stb + GC_ABUF + so, pB1 + go);                         \
        }                                                                \
        asm volatile("cp.async.commit_group;" ::: "memory");             \
    } while (0)

#define LOAD_CHUNK2(c, s)                                                \
    do {                                                                 \
        const uint32_t stb = sbase + (uint32_t)(s) * GC_STB;             \
        const size_t kt = (size_t)(c) << 6;                              \
        _Pragma("unroll")                                                \
        for (int i = 0; i < 2; i++) {                                    \
            int ch = tid + i * 256;                                      \
            int row = ch >> 3, kc = ch & 7;                              \
            size_t go = (size_t)row * H_DIM + kt + (size_t)kc * 8;       \
            uint32_t so = (uint32_t)(row * ROW_B + kc * 16);             \
            cpa16(stb + so, pA2 + go);                                   \
        }                                                                \
        _Pragma("unroll")                                                \
        for (int i = 0; i < 4; i++) {                                    \
            int ch = tid + i * 256;                                      \
            int row = ch >> 3, kc = ch & 7;                              \
            size_t go = (size_t)row * H_DIM + kt + (size_t)kc * 8;       \
            uint32_t so = (uint32_t)(row * ROW_B + kc * 16);             \
            cpa16(stb + GC_ABUF + so, pB2 + go);                         \
        }                                                                \
        asm volatile("cp.async.commit_group;" ::: "memory");             \
    } while (0)

#define CAT_LOAD(cc, ss)                                                 \
    do {                                                                 \
        int _c = (cc);                                                   \
        if (_c < NC1) LOAD_CHUNK1(_c, (ss));                             \
        else          LOAD_CHUNK2(_c - NC1, (ss));                       \
    } while (0)

    CAT_LOAD(0, 0);

    const uint32_t aRowOff = (uint32_t)(lane & 15) * ROW_B + ((lane >> 4) << 4);
    const uint32_t bRowOff = (uint32_t)((lane & 7) + ((lane >> 4) << 3)) * ROW_B +
                             (((lane >> 3) & 1) << 4);

    for (int c = 0; c < NCT; c++) {
        const int s = c & 1;
        asm volatile("cp.async.wait_group 0;" ::: "memory");
        __syncthreads();

        if (c + 1 < NCT) CAT_LOAD(c + 1, s ^ 1);

        const uint32_t stb = sbase + (uint32_t)s * GC_STB;
        const uint32_t aP = stb + (uint32_t)(wm * 32) * ROW_B + aRowOff;
        const uint32_t bP = stb + GC_ABUF + (uint32_t)(wn * 32) * ROW_B + bRowOff;

#pragma unroll
        for (int ks = 0; ks < 4; ks++) {
            const uint32_t kb = (uint32_t)ks * 32;
            uint32_t af[2][4], bb[4][2];
#pragma unroll
            for (int mi = 0; mi < 2; mi++)
                LDM4(af[mi], aP + (uint32_t)(mi * 16) * ROW_B + kb);
#pragma unroll
            for (int g = 0; g < 2; g++)
                LDM4(&bb[g * 2][0], bP + (uint32_t)(g * 16) * ROW_B + kb);

#pragma unroll
            for (int mi = 0; mi < 2; mi++)
#pragma unroll
                for (int ni = 0; ni < 4; ni++) MMA(d[mi][ni], af[mi], bb[ni]);
        }
    }
#undef CAT_LOAD
#undef LOAD_CHUNK1
#undef LOAD_CHUNK2

    // epilogue: pure fp32 write
    {
        const int r = lane >> 2;
        const int q = lane & 3;
#pragma unroll
        for (int mi = 0; mi < 2; mi++) {
            const size_t m0 = mBase + (size_t)(wm * 32 + mi * 16 + r);
#pragma unroll
            for (int ni = 0; ni < 4; ni++) {
                const size_t col = nBase + (size_t)(wn * 32 + ni * 8 + q * 2);
                float* dd = d[mi][ni];
                *(float2*)(Cf + m0 * N + col)       = make_float2(dd[0], dd[1]);
                *(float2*)(Cf + (m0 + 8) * N + col) = make_float2(dd[2], dd[3]);
            }
        }
    }
}

// ---------------- LayerNorm over H=1024 ----------------
__global__ __launch_bounds__(256)
void ln_kernel(const float* __restrict__ acc, const float* __restrict__ gamma,
               const float* __restrict__ beta, float* __restrict__ out) {
    size_t row = blockIdx.x;
    const float* xr = acc + row * H_DIM;
    int tid = threadIdx.x;

    float4 v = ((const float4*)xr)[tid];
    float s = v.x + v.y + v.z + v.w;
    float q = v.x * v.x + v.y * v.y + v.z * v.z + v.w * v.w;
#pragma unroll
    for (int o = 16; o > 0; o >>= 1) {
        s += __shfl_xor_sync(0xFFFFFFFFu, s, o);
        q += __shfl_xor_sync(0xFFFFFFFFu, q, o);
    }
    __shared__ float ss[8], qq[8];
    int w = tid >> 5, l = tid & 31;
    if (l == 0) { ss[w] = s; qq[w] = q; }
    __syncthreads();
    if (w == 0) {
        s = (l < 8) ? ss[l] : 0.0f;
        q = (l < 8) ? qq[l] : 0.0f;
#pragma unroll
        for (int o = 4; o > 0; o >>= 1) {
            s += __shfl_xor_sync(0xFFFFFFFFu, s, o);
            q += __shfl_xor_sync(0xFFFFFFFFu, q, o);
        }
        if (l == 0) { ss[0] = s; qq[0] = q; }
    }
    __syncthreads();

    const float invH = 1.0f / (float)H_DIM;
    float mean = ss[0] * invH;
    float var = qq[0] * invH - mean * mean;
    float inv = rsqrtf(var + 1e-5f);

    float4 g = ((const float4*)gamma)[tid];
    float4 b = ((const float4*)beta)[tid];
    float4 o4;
    o4.x = (v.x - mean) * inv * g.x + b.x;
    o4.y = (v.y - mean) * inv * g.y + b.y;
    o4.z = (v.z - mean) * inv * g.z + b.z;
    o4.w = (v.w - mean) * inv * g.w + b.w;
    ((float4*)(out + row * H_DIM))[tid] = o4;
}

// ---------------- launch ----------------
extern "C" void kernel_launch(void* const* d_in, const int* in_sizes, int n_in,
                              void* d_out, int out_size) {
    const float* x       = (const float*)d_in[0];
    const float* W_large = (const float*)d_in[1];
    const float* W_s1    = (const float*)d_in[2];
    const float* W_s2    = (const float*)d_in[3];
    const float* W_c1    = (const float*)d_in[4];
    const float* W_c2    = (const float*)d_in[5];
    const float* gamma   = (const float*)d_in[6];
    const float* beta    = (const float*)d_in[7];
    const float* s_large = (const float*)d_in[8];
    const float* s_s1    = (const float*)d_in[9];
    const float* s_s2    = (const float*)d_in[10];
    float* out = (float*)d_out;

    __half *pxh, *pWl, *pWs, *pc1, *pc2, *pb1, *pb2;
    float* pacc;
    cudaGetSymbolAddress((void**)&pxh, g_xh);
    cudaGetSymbolAddress((void**)&pWl, g_Wl);
    cudaGetSymbolAddress((void**)&pWs, g_Ws);
    cudaGetSymbolAddress((void**)&pc1, g_c1);
    cudaGetSymbolAddress((void**)&pc2, g_c2);
    cudaGetSymbolAddress((void**)&pb1, g_b1);
    cudaGetSymbolAddress((void**)&pb2, g_b2);
    cudaGetSymbolAddress((void**)&pacc, g_acc);

    cudaFuncSetAttribute(gemm_relu, cudaFuncAttributeMaxDynamicSharedMemorySize, GR_SMEM);
    cudaFuncSetAttribute(gemm_cat,  cudaFuncAttributeMaxDynamicSharedMemorySize, GC_SMEM);

    // L0: fused prep — all fp16 rounds/folds in one launch
    k_prep<<<NB_X + NB_WL + NB_C1 + NB_C2 + NB_WS, 256>>>(
        x, W_large, s_large, W_c1, W_c2, W_s1, s_s1, W_s2, s_s2,
        pxh, pWl, pc1, pc2, pWs);

    // L1: GEMM1: b1 = fp16(relu(x @ Wl^T))        [M,4096], K=1024
    gemm_relu<<<dim3(L_DIM / 128, M_TOT / 128), 512, GR_SMEM>>>(
        pxh, pWl, pb1, L_DIM, H_DIM);
    // L2: GEMM2: b2 = fp16(relu(b1 @ Wc1^T))      [M,4096], K=4096
    gemm_relu<<<dim3(L_DIM / 128, M_TOT / 128), 512, GR_SMEM>>>(
        pb1, pc1, pb2, L_DIM, L_DIM);
    // L3: fused GEMM3+GEMM4 (concatenated K), 64x128 tiles / 4 CTAs/SM:
    //     acc = b2 @ Wc2^T (K=4096)  +  x @ Wsum^T (K=1024)
    gemm_cat<<<dim3(H_DIM / 128, M_TOT / 64), 256, GC_SMEM>>>(
        pb2, pc2, pxh, pWs, pacc, H_DIM);
    // L4: LN
    ln_kernel<<<M_TOT, 256>>>(pacc, gamma, beta, out);
}

// round 17
// speedup vs baseline: 1.0150x; 1.0001x over previous
#include <cuda_runtime.h>
#include <cuda_fp16.h>
#include <cstdint>

#define M_TOT 32768
#define H_DIM 1024
#define L_DIM 4096

// ---------------- device scratch (no allocs allowed) ----------------
__device__ __half g_xh [(size_t)M_TOT * H_DIM];
__device__ __half g_Wl [(size_t)L_DIM * H_DIM];
__device__ __half g_Ws [(size_t)H_DIM * H_DIM];
__device__ __half g_c1 [(size_t)L_DIM * L_DIM];
__device__ __half g_c2 [(size_t)H_DIM * L_DIM];
__device__ __half g_b1 [(size_t)M_TOT * L_DIM];
__device__ __half g_b2 [(size_t)M_TOT * L_DIM];
__device__ float  g_acc[(size_t)M_TOT * H_DIM];

// ---------------- helpers ----------------
__device__ __forceinline__ uint32_t s2u(const void* p) {
    uint32_t a;
    asm("{ .reg .u64 t; cvta.to.shared.u64 t, %1; cvt.u32.u64 %0, t; }" : "=r"(a) : "l"(p));
    return a;
}

__device__ __forceinline__ void cpa16(uint32_t dst, const void* src) {
    asm volatile("cp.async.cg.shared.global [%0], [%1], 16;" :: "r"(dst), "l"(src));
}

#define LDM4(r, a)                                                               \
    asm volatile("ldmatrix.sync.aligned.m8n8.x4.shared.b16 {%0,%1,%2,%3}, [%4];" \
                 : "=r"((r)[0]), "=r"((r)[1]), "=r"((r)[2]), "=r"((r)[3])        \
                 : "r"(a))

#define MMA(dd, a, b)                                                             \
    asm volatile("mma.sync.aligned.m16n8k16.row.col.f32.f16.f16.f32 "             \
                 "{%0,%1,%2,%3},{%4,%5,%6,%7},{%8,%9},{%0,%1,%2,%3};"             \
                 : "+f"((dd)[0]), "+f"((dd)[1]), "+f"((dd)[2]), "+f"((dd)[3])     \
                 : "r"((a)[0]), "r"((a)[1]), "r"((a)[2]), "r"((a)[3]),            \
                   "r"((b)[0]), "r"((b)[1]))

// ---------------- prep kernels (split for stream overlap) --------------------
__device__ __forceinline__ uint2 round4h(float4 v) {
    __half2 h01 = __floats2half2_rn(v.x, v.y);
    __half2 h23 = __floats2half2_rn(v.z, v.w);
    uint2 hh;
    hh.x = *(uint32_t*)&h01; hh.y = *(uint32_t*)&h23;
    return hh;
}

// prep_a: x + W_large (needed by GEMM1)
#define NB_X  32768   // x: 32768x1024 /4/256
#define NB_WL 4096    // W_large: 4096x1024

__global__ void __launch_bounds__(256)
k_prep_a(const float* __restrict__ x,
         const float* __restrict__ W_large, const float* __restrict__ s_large,
         __half* __restrict__ xh, __half* __restrict__ Wl) {
    const int b = blockIdx.x;
    const int tid = threadIdx.x;
    if (b < NB_X) {
        size_t i = (size_t)b * 256 + tid;
        ((uint2*)xh)[i] = round4h(((const float4*)x)[i]);
    } else {
        size_t i = (size_t)(b - NB_X) * 256 + tid;
        size_t idx = i * 4;
        int o = (int)(idx / H_DIM), h = (int)(idx % H_DIM);
        float sc = s_large[(o >> 7) * (H_DIM >> 7) + (h >> 7)];
        float4 v = ((const float4*)W_large)[i];
        v.x *= sc; v.y *= sc; v.z *= sc; v.w *= sc;
        ((uint2*)Wl)[i] = round4h(v);
    }
}

// prep_b: W_c1 + W_c2 + Wsum (needed from GEMM2 onward; overlapped with GEMM1)
#define NB_C1 16384   // W_c1: 4096x4096
#define NB_C2 4096    // W_c2: 1024x4096
#define NB_WS 1024    // Wsum: 1024x1024

__global__ void __launch_bounds__(256)
k_prep_b(const float* __restrict__ W_c1, const float* __restrict__ W_c2,
         const float* __restrict__ W_s1, const float* __restrict__ s_s1,
         const float* __restrict__ W_s2, const float* __restrict__ s_s2,
         __half* __restrict__ c1, __half* __restrict__ c2, __half* __restrict__ Ws) {
    const int b = blockIdx.x;
    const int tid = threadIdx.x;
    if (b < NB_C1) {
        size_t i = (size_t)b * 256 + tid;
        ((uint2*)c1)[i] = round4h(((const float4*)W_c1)[i]);
    } else if (b < NB_C1 + NB_C2) {
        size_t i = (size_t)(b - NB_C1) * 256 + tid;
        ((uint2*)c2)[i] = round4h(((const float4*)W_c2)[i]);
    } else {
        size_t i = (size_t)(b - NB_C1 - NB_C2) * 256 + tid;
        size_t idx = i * 4;
        int o = (int)(idx / H_DIM), h = (int)(idx % H_DIM);
        int sb = (o >> 7) * (H_DIM >> 7) + (h >> 7);
        float a = s_s1[sb], bb = s_s2[sb];
        float4 v1 = ((const float4*)W_s1)[i];
        float4 v2 = ((const float4*)W_s2)[i];
        float4 v = make_float4(v1.x * a + v2.x * bb, v1.y * a + v2.y * bb,
                               v1.z * a + v2.z * bb, v1.w * a + v2.w * bb);
        ((uint2*)Ws)[i] = round4h(v);
    }
}

#define ROW_B 144

// ============ gemm_relu: R12/R14 golden config ============
// CTA tile 128x128, BK=64, 3-stage, 512 threads (16 warps 4x4), 2 CTAs/SM.
#define GR_BUF   (128 * ROW_B)        // 18432
#define GR_STB   (2 * GR_BUF)         // 36864
#define GR_NST   3
#define GR_SMEM  (GR_NST * GR_STB)    // 110592

__global__ void __launch_bounds__(512, 2)
gemm_relu(const __half* __restrict__ A, const __half* __restrict__ B,
          __half* __restrict__ Oh, int N, int K) {
    extern __shared__ char smem[];
    const uint32_t sbase = s2u(smem);

    const int tid = threadIdx.x;
    const int lane = tid & 31;
    const int w = tid >> 5;
    const int wm = w & 3;      // 4 warps in M (32 rows each)
    const int wn = w >> 2;     // 4 warps in N (32 cols each)

    const size_t mBase = (size_t)blockIdx.y * 128;
    const size_t nBase = (size_t)blockIdx.x * 128;
    const int NC = K >> 6;     // K-chunks of 64

    const __half* pA = A + mBase * K;
    const __half* pB = B + nBase * K;

    float d[2][4][4];
#pragma unroll
    for (int i = 0; i < 2; i++)
#pragma unroll
        for (int j = 0; j < 4; j++)
#pragma unroll
            for (int q = 0; q < 4; q++) d[i][j][q] = 0.0f;

#define LOAD_CHUNK(c, s)                                                 \
    do {                                                                 \
        const uint32_t stb = sbase + (uint32_t)(s) * GR_STB;             \
        const size_t kt = (size_t)(c) << 6;                              \
        _Pragma("unroll")                                                \
        for (int i = 0; i < 2; i++) {                                    \
            int ch = tid + i * 512;                                      \
            int row = ch >> 3, kc = ch & 7;                              \
            size_t go = (size_t)row * K + kt + (size_t)kc * 8;           \
            uint32_t so = (uint32_t)(row * ROW_B + kc * 16);             \
            cpa16(stb + so,          pA + go);                           \
            cpa16(stb + GR_BUF + so, pB + go);                           \
        }                                                                \
        asm volatile("cp.async.commit_group;" ::: "memory");             \
    } while (0)

    LOAD_CHUNK(0, 0);
    LOAD_CHUNK(1, 1);

    const uint32_t aRowOff = (uint32_t)(lane & 15) * ROW_B + ((lane >> 4) << 4);
    const uint32_t bRowOff = (uint32_t)((lane & 7) + ((lane >> 4) << 3)) * ROW_B +
                             (((lane >> 3) & 1) << 4);

    for (int c = 0; c < NC; c++) {
        const int s = c % GR_NST;
        if (c + 1 < NC) asm volatile("cp.async.wait_group 1;" ::: "memory");
        else            asm volatile("cp.async.wait_group 0;" ::: "memory");
        __syncthreads();

        if (c + 2 < NC) LOAD_CHUNK(c + 2, (c + 2) % GR_NST);

        const uint32_t stb = sbase + (uint32_t)s * GR_STB;
        const uint32_t aP = stb + (uint32_t)(wm * 32) * ROW_B + aRowOff;
        const uint32_t bP = stb + GR_BUF + (uint32_t)(wn * 32) * ROW_B + bRowOff;

#pragma unroll
        for (int ks = 0; ks < 4; ks++) {
            const uint32_t kb = (uint32_t)ks * 32;
            uint32_t af[2][4], bb[4][2];
#pragma unroll
            for (int mi = 0; mi < 2; mi++)
                LDM4(af[mi], aP + (uint32_t)(mi * 16) * ROW_B + kb);
#pragma unroll
            for (int g = 0; g < 2; g++)
                LDM4(&bb[g * 2][0], bP + (uint32_t)(g * 16) * ROW_B + kb);

#pragma unroll
            for (int mi = 0; mi < 2; mi++)
#pragma unroll
                for (int ni = 0; ni < 4; ni++) MMA(d[mi][ni], af[mi], bb[ni]);
        }
    }
#undef LOAD_CHUNK

    // epilogue: relu + fp16
    {
        const int r = lane >> 2;
        const int q = lane & 3;
#pragma unroll
        for (int mi = 0; mi < 2; mi++) {
            const size_t m0 = mBase + (size_t)(wm * 32 + mi * 16 + r);
#pragma unroll
            for (int ni = 0; ni < 4; ni++) {
                const size_t col = nBase + (size_t)(wn * 32 + ni * 8 + q * 2);
                float* dd = d[mi][ni];
                float v0 = fmaxf(dd[0], 0.0f), v1 = fmaxf(dd[1], 0.0f);
                float v2 = fmaxf(dd[2], 0.0f), v3 = fmaxf(dd[3], 0.0f);
                *(__half2*)(Oh + m0 * N + col)       = __floats2half2_rn(v0, v1);
                *(__half2*)(Oh + (m0 + 8) * N + col) = __floats2half2_rn(v2, v3);
            }
        }
    }
}

// ============ gemm_cat: R15 golden config ============
// CTA tile 64(M) x 128(N), BK=64, 2-stage, 256 threads (8 warps 2x4), 4 CTAs/SM.
// Cf = A1 @ B1^T (K=L_DIM) + A2 @ B2^T (K=H_DIM), fp32 out.
#define GC_ABUF  (64 * ROW_B)         // 9216
#define GC_BBUF  (128 * ROW_B)        // 18432
#define GC_STB   (GC_ABUF + GC_BBUF)  // 27648
#define GC_SMEM  (2 * GC_STB)         // 55296

__global__ void __launch_bounds__(256, 4)
gemm_cat(const __half* __restrict__ A1, const __half* __restrict__ B1,
         const __half* __restrict__ A2, const __half* __restrict__ B2,
         float* __restrict__ Cf, int N) {
    extern __shared__ char smem[];
    const uint32_t sbase = s2u(smem);

    const int tid = threadIdx.x;
    const int lane = tid & 31;
    const int w = tid >> 5;
    const int wm = w & 1;
    const int wn = w >> 1;

    const size_t mBase = (size_t)blockIdx.y * 64;
    const size_t nBase = (size_t)blockIdx.x * 128;
    const int NC1 = L_DIM >> 6;               // 64
    const int NCT = NC1 + (H_DIM >> 6);       // 80

    const __half* pA1 = A1 + mBase * L_DIM;
    const __half* pB1 = B1 + nBase * L_DIM;
    const __half* pA2 = A2 + mBase * H_DIM;
    const __half* pB2 = B2 + nBase * H_DIM;

    float d[2][4][4];
#pragma unroll
    for (int i = 0; i < 2; i++)
#pragma unroll
        for (int j = 0; j < 4; j++)
#pragma unroll
            for (int q = 0; q < 4; q++) d[i][j][q] = 0.0f;

#define LOAD_CHUNK1(c, s)                                                \
    do {                                                                 \
        const uint32_t stb = sbase + (uint32_t)(s) * GC_STB;             \
        const size_t kt = (size_t)(c) << 6;                              \
        _Pragma("unroll")                                                \
        for (int i = 0; i < 2; i++) {                                    \
            int ch = tid + i * 256;                                      \
            int row = ch >> 3, kc = ch & 7;                              \
            size_t go = (size_t)row * L_DIM + kt + (size_t)kc * 8;       \
            uint32_t so = (uint32_t)(row * ROW_B + kc * 16);             \
            cpa16(stb + so, pA1 + go);                                   \
        }                                                                \
        _Pragma("unroll")                                                \
        for (int i = 0; i < 4; i++) {                                    \
            int ch = tid + i * 256;                                      \
            int row = ch >> 3, kc = ch & 7;                              \
            size_t go = (size_t)row * L_DIM + kt + (size_t)kc * 8;       \
            uint32_t so = (uint32_t)(row * ROW_B + kc * 16);             \
            cpa16(stb + GC_ABUF + so, pB1 + go);                         \
        }                                                                \
        asm volatile("cp.async.commit_group;" ::: "memory");             \
    } while (0)

#define LOAD_CHUNK2(c, s)                                                \
    do {                                                                 \
        const uint32_t stb = sbase + (uint32_t)(s) * GC_STB;             \
        const size_t kt = (size_t)(c) << 6;                              \
        _Pragma("unroll")                                                \
        for (int i = 0; i < 2; i++) {                                    \
            int ch = tid + i * 256;                                      \
            int row = ch >> 3, kc = ch & 7;                              \
            size_t go = (size_t)row * H_DIM + kt + (size_t)kc * 8;       \
            uint32_t so = (uint32_t)(row * ROW_B + kc * 16);             \
            cpa16(stb + so, pA2 + go);                                   \
        }                                                                \
        _Pragma("unroll")                                                \
        for (int i = 0; i < 4; i++) {                                    \
            int ch = tid + i * 256;                                      \
            int row = ch >> 3, kc = ch & 7;                              \
            size_t go = (size_t)row * H_DIM + kt + (size_t)kc * 8;       \
            uint32_t so = (uint32_t)(row * ROW_B + kc * 16);             \
            cpa16(stb + GC_ABUF + so, pB2 + go);                         \
        }                                                                \
        asm volatile("cp.async.commit_group;" ::: "memory");             \
    } while (0)

#define CAT_LOAD(cc, ss)                                                 \
    do {                                                                 \
        int _c = (cc);                                                   \
        if (_c < NC1) LOAD_CHUNK1(_c, (ss));                             \
        else          LOAD_CHUNK2(_c - NC1, (ss));                       \
    } while (0)

    CAT_LOAD(0, 0);

    const uint32_t aRowOff = (uint32_t)(lane & 15) * ROW_B + ((lane >> 4) << 4);
    const uint32_t bRowOff = (uint32_t)((lane & 7) + ((lane >> 4) << 3)) * ROW_B +
                             (((lane >> 3) & 1) << 4);

    for (int c = 0; c < NCT; c++) {
        const int s = c & 1;
        asm volatile("cp.async.wait_group 0;" ::: "memory");
        __syncthreads();

        if (c + 1 < NCT) CAT_LOAD(c + 1, s ^ 1);

        const uint32_t stb = sbase + (uint32_t)s * GC_STB;
        const uint32_t aP = stb + (uint32_t)(wm * 32) * ROW_B + aRowOff;
        const uint32_t bP = stb + GC_ABUF + (uint32_t)(wn * 32) * ROW_B + bRowOff;

#pragma unroll
        for (int ks = 0; ks < 4; ks++) {
            const uint32_t kb = (uint32_t)ks * 32;
            uint32_t af[2][4], bb[4][2];
#pragma unroll
            for (int mi = 0; mi < 2; mi++)
                LDM4(af[mi], aP + (uint32_t)(mi * 16) * ROW_B + kb);
#pragma unroll
            for (int g = 0; g < 2; g++)
                LDM4(&bb[g * 2][0], bP + (uint32_t)(g * 16) * ROW_B + kb);

#pragma unroll
            for (int mi = 0; mi < 2; mi++)
#pragma unroll
                for (int ni = 0; ni < 4; ni++) MMA(d[mi][ni], af[mi], bb[ni]);
        }
    }
#undef CAT_LOAD
#undef LOAD_CHUNK1
#undef LOAD_CHUNK2

    // epilogue: pure fp32 write
    {
        const int r = lane >> 2;
        const int q = lane & 3;
#pragma unroll
        for (int mi = 0; mi < 2; mi++) {
            const size_t m0 = mBase + (size_t)(wm * 32 + mi * 16 + r);
#pragma unroll
            for (int ni = 0; ni < 4; ni++) {
                const size_t col = nBase + (size_t)(wn * 32 + ni * 8 + q * 2);
                float* dd = d[mi][ni];
                *(float2*)(Cf + m0 * N + col)       = make_float2(dd[0], dd[1]);
                *(float2*)(Cf + (m0 + 8) * N + col) = make_float2(dd[2], dd[3]);
            }
        }
    }
}

// ---------------- LayerNorm over H=1024 ----------------
__global__ __launch_bounds__(256)
void ln_kernel(const float* __restrict__ acc, const float* __restrict__ gamma,
               const float* __restrict__ beta, float* __restrict__ out) {
    size_t row = blockIdx.x;
    const float* xr = acc + row * H_DIM;
    int tid = threadIdx.x;

    float4 v = ((const float4*)xr)[tid];
    float s = v.x + v.y + v.z + v.w;
    float q = v.x * v.x + v.y * v.y + v.z * v.z + v.w * v.w;
#pragma unroll
    for (int o = 16; o > 0; o >>= 1) {
        s += __shfl_xor_sync(0xFFFFFFFFu, s, o);
        q += __shfl_xor_sync(0xFFFFFFFFu, q, o);
    }
    __shared__ float ss[8], qq[8];
    int w = tid >> 5, l = tid & 31;
    if (l == 0) { ss[w] = s; qq[w] = q; }
    __syncthreads();
    if (w == 0) {
        s = (l < 8) ? ss[l] : 0.0f;
        q = (l < 8) ? qq[l] : 0.0f;
#pragma unroll
        for (int o = 4; o > 0; o >>= 1) {
            s += __shfl_xor_sync(0xFFFFFFFFu, s, o);
            q += __shfl_xor_sync(0xFFFFFFFFu, q, o);
        }
        if (l == 0) { ss[0] = s; qq[0] = q; }
    }
    __syncthreads();

    const float invH = 1.0f / (float)H_DIM;
    float mean = ss[0] * invH;
    float var = qq[0] * invH - mean * mean;
    float inv = rsqrtf(var + 1e-5f);

    float4 g = ((const float4*)gamma)[tid];
    float4 b = ((const float4*)beta)[tid];
    float4 o4;
    o4.x = (v.x - mean) * inv * g.x + b.x;
    o4.y = (v.y - mean) * inv * g.y + b.y;
    o4.z = (v.z - mean) * inv * g.z + b.z;
    o4.w = (v.w - mean) * inv * g.w + b.w;
    ((float4*)(out + row * H_DIM))[tid] = o4;
}

// ---------------- launch ----------------
extern "C" void kernel_launch(void* const* d_in, const int* in_sizes, int n_in,
                              void* d_out, int out_size) {
    const float* x       = (const float*)d_in[0];
    const float* W_large = (const float*)d_in[1];
    const float* W_s1    = (const float*)d_in[2];
    const float* W_s2    = (const float*)d_in[3];
    const float* W_c1    = (const float*)d_in[4];
    const float* W_c2    = (const float*)d_in[5];
    const float* gamma   = (const float*)d_in[6];
    const float* beta    = (const float*)d_in[7];
    const float* s_large = (const float*)d_in[8];
    const float* s_s1    = (const float*)d_in[9];
    const float* s_s2    = (const float*)d_in[10];
    float* out = (float*)d_out;

    __half *pxh, *pWl, *pWs, *pc1, *pc2, *pb1, *pb2;
    float* pacc;
    cudaGetSymbolAddress((void**)&pxh, g_xh);
    cudaGetSymbolAddress((void**)&pWl, g_Wl);
    cudaGetSymbolAddress((void**)&pWs, g_Ws);
    cudaGetSymbolAddress((void**)&pc1, g_c1);
    cudaGetSymbolAddress((void**)&pc2, g_c2);
    cudaGetSymbolAddress((void**)&pb1, g_b1);
    cudaGetSymbolAddress((void**)&pb2, g_b2);
    cudaGetSymbolAddress((void**)&pacc, g_acc);

    cudaFuncSetAttribute(gemm_relu, cudaFuncAttributeMaxDynamicSharedMemorySize, GR_SMEM);
    cudaFuncSetAttribute(gemm_cat,  cudaFuncAttributeMaxDynamicSharedMemorySize, GC_SMEM);

    // Fork-join: prep_b (weights for GEMM2/cat) runs concurrently with
    // prep_a + GEMM1 on a second stream inside the captured graph.
    cudaStream_t s2;
    cudaEvent_t evFork, evJoin;
    cudaStreamCreateWithFlags(&s2, cudaStreamNonBlocking);
    cudaEventCreateWithFlags(&evFork, cudaEventDisableTiming);
    cudaEventCreateWithFlags(&evJoin, cudaEventDisableTiming);

    cudaEventRecord(evFork, 0);              // fork point on capture (default) stream
    cudaStreamWaitEvent(s2, evFork, 0);

    // side stream: prep_b (c1, c2, Wsum)
    k_prep_b<<<NB_C1 + NB_C2 + NB_WS, 256, 0, s2>>>(
        W_c1, W_c2, W_s1, s_s1, W_s2, s_s2, pc1, pc2, pWs);
    cudaEventRecord(evJoin, s2);

    // main stream: prep_a (x, W_large) then GEMM1
    k_prep_a<<<NB_X + NB_WL, 256>>>(x, W_large, s_large, pxh, pWl);
    gemm_relu<<<dim3(L_DIM / 128, M_TOT / 128), 512, GR_SMEM>>>(
        pxh, pWl, pb1, L_DIM, H_DIM);

    // join: GEMM2 needs c1 (and cat later needs c2/Ws)
    cudaStreamWaitEvent(0, evJoin, 0);

    // GEMM2: b2 = fp16(relu(b1 @ Wc1^T))      [M,4096], K=4096
    gemm_relu<<<dim3(L_DIM / 128, M_TOT / 128), 512, GR_SMEM>>>(
        pb1, pc1, pb2, L_DIM, L_DIM);
    // fused GEMM3+GEMM4 (concatenated K), 64x128 tiles / 4 CTAs/SM:
    //     acc = b2 @ Wc2^T (K=4096)  +  x @ Wsum^T (K=1024)
    gemm_cat<<<dim3(H_DIM / 128, M_TOT / 64), 256, GC_SMEM>>>(
        pb2, pc2, pxh, pWs, pacc, H_DIM);
    // LN
    ln_kernel<<<M_TOT, 256>>>(pacc, gamma, beta, out);
}